// round 8
// baseline (speedup 1.0000x reference)
#include <cuda_runtime.h>
#include <math.h>

#define B_ 8
#define N_ 512
#define C_ 1024
#define H_ 16
#define D_ 64
#define L_ 8
#define BN_ (B_*N_)
#define BNC_ (B_*N_*C_)
#define MODR_ (L_*6*C_)      // total mod rows across all layers

// ---------------------------------------------------------------- f32x2 helpers
__device__ __forceinline__ unsigned long long pk2(float lo, float hi){
    unsigned long long r;
    asm("mov.b64 %0, {%1,%2};" : "=l"(r) : "f"(lo), "f"(hi));
    return r;
}
__device__ __forceinline__ void upk2(unsigned long long v, float& lo, float& hi){
    asm("mov.b64 {%0,%1}, %2;" : "=f"(lo), "=f"(hi) : "l"(v));
}
__device__ __forceinline__ unsigned long long fma2(unsigned long long a, unsigned long long b, unsigned long long c){
    unsigned long long d;
    asm("fma.rn.f32x2 %0, %1, %2, %3;" : "=l"(d) : "l"(a), "l"(b), "l"(c));
    return d;
}
__device__ __forceinline__ unsigned long long mul2(unsigned long long a, unsigned long long b){
    unsigned long long d;
    asm("mul.rn.f32x2 %0, %1, %2;" : "=l"(d) : "l"(a), "l"(b));
    return d;
}

__device__ __forceinline__ float selu_f(float x){
    return 1.0507009873554805f * (x > 0.0f ? x : 1.6732632423543772f * expm1f(x));
}

// ---------------------------------------------------------------- scratch (no allocs allowed)
__device__ __align__(256) float g_xc [BNC_];
__device__ __align__(256) float g_h  [BNC_];
__device__ __align__(256) float g_q  [BNC_];
__device__ __align__(256) float g_k  [BNC_];
__device__ __align__(256) float g_v  [BNC_];
__device__ __align__(256) float g_att[BNC_];
__device__ __align__(256) float g_mid[B_*N_*4*C_];
__device__ __align__(256) float g_ffn[BNC_];
__device__ __align__(256) float g_c  [B_*C_];
__device__ __align__(256) float g_cs [B_*C_];
__device__ __align__(256) float g_modall[B_*MODR_];   // all layers' mod vectors [B][L*6C]
__device__ __align__(256) float g_modf[B_*2*C_];      // final-projection mod

// ---------------------------------------------------------------- conditioning: c = lemb + time-embedding, plus selu(c)
__global__ void cond_kernel(const float* __restrict__ timep, const float* __restrict__ label,
                            const float* __restrict__ Wl, const float* __restrict__ bl,
                            float* __restrict__ c_out, float* __restrict__ cs_out)
{
    int idx = blockIdx.x * 256 + threadIdx.x;   // B_*C_ = 8192 threads
    if (idx >= B_*C_) return;
    int b = idx >> 10, j = idx & (C_-1);
    float lemb = label[b*2+0]*Wl[j*2+0] + label[b*2+1]*Wl[j*2+1] + bl[j];
    const float LOG1E4 = 9.210340371976184f;
    float base = expf((2.0f * (float)j / (float)C_) * LOG1E4);
    float te = timep[b] / base;
    te = ((j & 1) == 0) ? sinf(te) : cosf(te);
    float cv = lemb + te;
    c_out[idx]  = cv;
    cs_out[idx] = selu_f(cv);
}

// ---------------------------------------------------------------- mod = selu(c) @ W.T + b  (rows x K=1024, B=8 batches)
// W contiguous [rows, C]; out layout [B][rows]
__global__ void mod_gemm(const float* __restrict__ scv, const float* __restrict__ W,
                         const float* __restrict__ bias, float* __restrict__ out, int rows)
{
    __shared__ float s[B_*C_];      // 32 KB: selu(c), all batches
    int t = threadIdx.x;            // 256
    for (int i = t; i < B_*C_; i += 256) s[i] = scv[i];
    __syncthreads();
    int warp = t >> 5, lane = t & 31;
    int r = blockIdx.x * 8 + warp;
    if (r >= rows) return;
    float acc[B_] = {0,0,0,0,0,0,0,0};
    const float* wr = W + (size_t)r * C_;
    for (int k0 = lane*4; k0 < C_; k0 += 128){
        float4 w4 = *(const float4*)(wr + k0);
        #pragma unroll
        for (int b = 0; b < B_; b++){
            const float* sb = s + b*C_ + k0;
            acc[b] += w4.x*sb[0] + w4.y*sb[1] + w4.z*sb[2] + w4.w*sb[3];
        }
    }
    #pragma unroll
    for (int b = 0; b < B_; b++){
        #pragma unroll
        for (int off = 16; off > 0; off >>= 1)
            acc[b] += __shfl_down_sync(0xffffffffu, acc[b], off);
    }
    if (lane == 0){
        float bb = bias[r];
        #pragma unroll
        for (int b = 0; b < B_; b++) out[b*rows + r] = acc[b] + bb;
    }
}

// ---------------------------------------------------------------- fused [gated residual +] LayerNorm + modulate
// value read from resin; if src != nullptr:  val = (resin + g*src) [* xm_res], persisted to xcin
// then h = modulate(LN(val), shift, scale) [* xm_h]
__global__ void ln_mod(const float* __restrict__ resin, float* __restrict__ xcin,
                       float* __restrict__ out,
                       const float* __restrict__ mod, int shift_ofs, int scale_ofs, int modstride,
                       const float* __restrict__ xm_h,
                       const float* __restrict__ src,
                       const float* __restrict__ gmod, int gofs, int gstride,
                       const float* __restrict__ xm_res)
{
    __shared__ float rs[8], rq[8];
    int bn = blockIdx.x;            // B*N rows
    int b  = bn >> 9;
    const float* rin = resin + ((size_t)bn << 10);
    float* row = xcin + ((size_t)bn << 10);
    int t = threadIdx.x;            // 256
    const float* gp = gmod ? (gmod + (size_t)b*gstride + gofs) : nullptr;
    float mres = xm_res ? xm_res[bn] : 1.0f;
    float v[4]; float s = 0.f, sq = 0.f;
    #pragma unroll
    for (int i = 0; i < 4; i++){
        int j = t + 256*i;
        float xv = rin[j];
        if (src){
            xv = (xv + gp[j] * src[((size_t)bn << 10) + j]) * mres;
            row[j] = xv;                    // persist updated residual stream
        }
        v[i] = xv; s += xv; sq += xv*xv;
    }
    #pragma unroll
    for (int off = 16; off > 0; off >>= 1){
        s  += __shfl_down_sync(0xffffffffu, s,  off);
        sq += __shfl_down_sync(0xffffffffu, sq, off);
    }
    int warp = t >> 5, lane = t & 31;
    if (lane == 0){ rs[warp] = s; rq[warp] = sq; }
    __syncthreads();
    float S = 0.f, Q = 0.f;
    #pragma unroll
    for (int i = 0; i < 8; i++){ S += rs[i]; Q += rq[i]; }
    float mean = S * (1.0f/C_);
    float var  = Q * (1.0f/C_) - mean*mean;
    float rstd = rsqrtf(var + 1e-6f);
    float mk = xm_h ? xm_h[bn] : 1.0f;
    const float* shp = mod + (size_t)b*modstride + shift_ofs;
    const float* scp = mod + (size_t)b*modstride + scale_ofs;
    float* orow = out + ((size_t)bn << 10);
    #pragma unroll
    for (int i = 0; i < 4; i++){
        int j = t + 256*i;
        float val = (v[i] - mean) * rstd * (1.0f + scp[j]) + shp[j];
        orow[j] = val * mk;
    }
}

// ---------------------------------------------------------------- GEMM core (NT, f32x2 accum, double-buffered smem, K-slice 16)
__device__ __forceinline__ void gemm_tile(const float* __restrict__ A, const float* __restrict__ W,
                                          int K, int bx, int by,
                                          float (*As)[132], float (*Bs)[132],   // [2*16][132] each
                                          unsigned long long (&acc)[8][4])
{
    int t  = threadIdx.x;
    int lr = t >> 1;                 // 0..127 (row)
    int lc = (t & 1) << 2;           // 0 or 4; each thread covers cols lc..lc+3 and lc+8..lc+11
    int tx = t & 15, ty = t >> 4;
    const float* Ag = A + ((size_t)by*128 + lr) * K + lc;
    const float* Wg = W + ((size_t)bx*128 + lr) * K + lc;
    #pragma unroll
    for (int i = 0; i < 8; i++)
        #pragma unroll
        for (int j = 0; j < 4; j++) acc[i][j] = 0ULL;

    // prologue: fetch slice 0 (16 wide = 2 float4 per matrix per thread)
    float4 a4  = *(const float4*)(Ag);
    float4 a4h = *(const float4*)(Ag + 8);
    float4 b4  = *(const float4*)(Wg);
    float4 b4h = *(const float4*)(Wg + 8);

    int buf = 0;
    for (int k0 = 0; k0 < K; k0 += 16){
        float (*Asb)[132] = As + buf*16;
        float (*Bsb)[132] = Bs + buf*16;
        Asb[lc+0][lr]=a4.x;  Asb[lc+1][lr]=a4.y;  Asb[lc+2][lr]=a4.z;  Asb[lc+3][lr]=a4.w;
        Asb[lc+8][lr]=a4h.x; Asb[lc+9][lr]=a4h.y; Asb[lc+10][lr]=a4h.z; Asb[lc+11][lr]=a4h.w;
        Bsb[lc+0][lr]=b4.x;  Bsb[lc+1][lr]=b4.y;  Bsb[lc+2][lr]=b4.z;  Bsb[lc+3][lr]=b4.w;
        Bsb[lc+8][lr]=b4h.x; Bsb[lc+9][lr]=b4h.y; Bsb[lc+10][lr]=b4h.z; Bsb[lc+11][lr]=b4h.w;
        __syncthreads();

        if (k0 + 16 < K){
            a4  = *(const float4*)(Ag + k0 + 16);
            a4h = *(const float4*)(Ag + k0 + 24);
            b4  = *(const float4*)(Wg + k0 + 16);
            b4h = *(const float4*)(Wg + k0 + 24);
        }

        #pragma unroll
        for (int kk = 0; kk < 16; kk++){
            float4 af0 = *(const float4*)&Asb[kk][ty*8];
            float4 af1 = *(const float4*)&Asb[kk][ty*8+4];
            ulonglong2 bl0 = *(const ulonglong2*)&Bsb[kk][tx*8];
            ulonglong2 bl1 = *(const ulonglong2*)&Bsb[kk][tx*8+4];
            unsigned long long bv[4] = {bl0.x, bl0.y, bl1.x, bl1.y};
            float af[8] = {af0.x,af0.y,af0.z,af0.w,af1.x,af1.y,af1.z,af1.w};
            #pragma unroll
            for (int i = 0; i < 8; i++){
                unsigned long long ai = pk2(af[i], af[i]);
                #pragma unroll
                for (int j = 0; j < 4; j++) acc[i][j] = fma2(ai, bv[j], acc[i][j]);
            }
        }
        buf ^= 1;   // WAR-safe: barrier-i guarantees compute i-1 done
    }
}

// general single-output GEMM with fused epilogue
__global__ void __launch_bounds__(256, 2)
sgemm_nt(const float* __restrict__ A, const float* __restrict__ W,
         const float* __restrict__ bias, const float* __restrict__ rowmask,
         float* __restrict__ Cmat, int M, int Ncols, int K, int act)
{
    __shared__ __align__(16) float As[32][132];
    __shared__ __align__(16) float Bs[32][132];
    unsigned long long acc[8][4];
    gemm_tile(A, W, K, blockIdx.x, blockIdx.y, As, Bs, acc);

    int t = threadIdx.x, tx = t & 15, ty = t >> 4;
    int row0 = blockIdx.y*128 + ty*8;
    int col0 = blockIdx.x*128 + tx*8;
    #pragma unroll
    for (int i = 0; i < 8; i++){
        int row = row0 + i;
        float mk = rowmask ? rowmask[row] : 1.0f;
        float o[8];
        #pragma unroll
        for (int j = 0; j < 4; j++) upk2(acc[i][j], o[2*j], o[2*j+1]);
        #pragma unroll
        for (int j = 0; j < 8; j++){
            float val = o[j];
            if (bias) val += bias[col0 + j];
            if (act)  val = selu_f(val);
            o[j] = val * mk;
        }
        *(float4*)(Cmat + (size_t)row*Ncols + col0)     = make_float4(o[0],o[1],o[2],o[3]);
        *(float4*)(Cmat + (size_t)row*Ncols + col0 + 4) = make_float4(o[4],o[5],o[6],o[7]);
    }
}

// fused Q/K/V projection: blockIdx.z in {0,1,2} selects weight + destination
__global__ void __launch_bounds__(256, 2)
sgemm_qkv(const float* __restrict__ A,
          const float* __restrict__ Wq, const float* __restrict__ Wk, const float* __restrict__ Wv,
          float* __restrict__ Qo, float* __restrict__ Ko, float* __restrict__ Vo)
{
    __shared__ __align__(16) float As[32][132];
    __shared__ __align__(16) float Bs[32][132];
    const float* W = (blockIdx.z == 0) ? Wq : (blockIdx.z == 1) ? Wk : Wv;
    float* Cmat    = (blockIdx.z == 0) ? Qo : (blockIdx.z == 1) ? Ko : Vo;
    unsigned long long acc[8][4];
    gemm_tile(A, W, C_, blockIdx.x, blockIdx.y, As, Bs, acc);

    int t = threadIdx.x, tx = t & 15, ty = t >> 4;
    int row0 = blockIdx.y*128 + ty*8;
    int col0 = blockIdx.x*128 + tx*8;
    #pragma unroll
    for (int i = 0; i < 8; i++){
        int row = row0 + i;
        float o[8];
        #pragma unroll
        for (int j = 0; j < 4; j++) upk2(acc[i][j], o[2*j], o[2*j+1]);
        *(float4*)(Cmat + (size_t)row*C_ + col0)     = make_float4(o[0],o[1],o[2],o[3]);
        *(float4*)(Cmat + (size_t)row*C_ + col0 + 4) = make_float4(o[4],o[5],o[6],o[7]);
    }
}

// ---------------------------------------------------------------- flash attention
// grid (N/32 q-tiles, B*H). 128 threads: 32 rows x 4 lane-groups. 64-key tiles.
#define AP 68   // smem row pad (floats): conflict-free & 16B-aligned
__global__ void __launch_bounds__(128, 4)
attn_kernel(const float* __restrict__ Qg, const float* __restrict__ Kg,
            const float* __restrict__ Vg, const float* __restrict__ xm,
            float* __restrict__ Og)
{
    __shared__ __align__(16) float Qs [32*AP];
    __shared__ __align__(16) float KVs[64*AP];
    __shared__ __align__(16) float Ps [32*AP];
    __shared__ float xmk[64];

    int qt = blockIdx.x;          // 0..15
    int bh = blockIdx.y;          // 0..127
    int b = bh >> 4, h = bh & 15;
    int t = threadIdx.x;          // 128
    const float inv_tp = rsqrtf(2.0f * (float)D_);

    size_t base = ((size_t)b * N_) * C_ + (size_t)h * D_;

    // load Q tile (32 x 64), pre-scaled by 1/sqrt(2D)
    for (int i = t; i < 32*16; i += 128){
        int r = i >> 4, d4 = i & 15;
        float4 qv = *(const float4*)(Qg + base + (size_t)(qt*32 + r)*C_ + d4*4);
        qv.x *= inv_tp; qv.y *= inv_tp; qv.z *= inv_tp; qv.w *= inv_tp;
        *(float4*)(Qs + r*AP + d4*4) = qv;
    }
    int row = t >> 2, g = t & 3;
    float xq = xm[b*N_ + qt*32 + row];
    float m_i = -INFINITY, l_i = 0.0f;
    unsigned long long o2[8];
    #pragma unroll
    for (int i = 0; i < 8; i++) o2[i] = 0ULL;
    __syncthreads();

    for (int kt = 0; kt < 8; kt++){
        // ---- load K tile (64 x 64)
        for (int i = t; i < 64*16; i += 128){
            int r = i >> 4, d4 = i & 15;
            *(float4*)(KVs + r*AP + d4*4) =
                *(const float4*)(Kg + base + (size_t)(kt*64 + r)*C_ + d4*4);
        }
        if (t < 64) xmk[t] = xm[b*N_ + kt*64 + t];
        __syncthreads();

        // ---- S = Q K^T : each thread -> 16 keys (j = g + 4*jj), f32x2 packed over d
        unsigned long long s2[16];
        #pragma unroll
        for (int jj = 0; jj < 16; jj++) s2[jj] = 0ULL;
        #pragma unroll
        for (int d4 = 0; d4 < 16; d4++){
            ulonglong2 q2 = *(const ulonglong2*)(Qs + row*AP + d4*4);
            #pragma unroll
            for (int jj = 0; jj < 16; jj++){
                ulonglong2 k2 = *(const ulonglong2*)(KVs + (g + 4*jj)*AP + d4*4);
                s2[jj] = fma2(q2.x, k2.x, s2[jj]);
                s2[jj] = fma2(q2.y, k2.y, s2[jj]);
            }
        }
        float sv[16]; float tmax = -INFINITY;
        #pragma unroll
        for (int jj = 0; jj < 16; jj++){
            float lo, hi; upk2(s2[jj], lo, hi);
            float val = lo + hi;
            if (xq + xmk[g + 4*jj] == 1.0f) val = -INFINITY;
            sv[jj] = val;
            tmax = fmaxf(tmax, val);
        }
        tmax = fmaxf(tmax, __shfl_xor_sync(0xffffffffu, tmax, 1));
        tmax = fmaxf(tmax, __shfl_xor_sync(0xffffffffu, tmax, 2));
        float m_new = fmaxf(m_i, tmax);
        float f, tsum = 0.0f;
        if (m_new == -INFINITY){
            f = 1.0f;
            #pragma unroll
            for (int jj = 0; jj < 16; jj++) Ps[row*AP + g + 4*jj] = 0.0f;
        } else {
            f = __expf(m_i - m_new);
            #pragma unroll
            for (int jj = 0; jj < 16; jj++){
                float p = __expf(sv[jj] - m_new);
                tsum += p;
                Ps[row*AP + g + 4*jj] = p;
            }
        }
        tsum += __shfl_xor_sync(0xffffffffu, tsum, 1);
        tsum += __shfl_xor_sync(0xffffffffu, tsum, 2);
        m_i = m_new;
        l_i = l_i * f + tsum;
        {
            unsigned long long ff = pk2(f, f);
            #pragma unroll
            for (int i = 0; i < 8; i++) o2[i] = mul2(o2[i], ff);
        }
        __syncthreads();   // everyone done with K; Ps visible

        // ---- load V tile into same buffer
        for (int i = t; i < 64*16; i += 128){
            int r = i >> 4, d4 = i & 15;
            *(float4*)(KVs + r*AP + d4*4) =
                *(const float4*)(Vg + base + (size_t)(kt*64 + r)*C_ + d4*4);
        }
        __syncthreads();

        // ---- O += P V : thread owns d-cols [g*16, g*16+16)
        for (int kk = 0; kk < 64; kk++){
            float p = Ps[row*AP + kk];
            unsigned long long pp = pk2(p, p);
            const float* vp = KVs + kk*AP + g*16;
            ulonglong2 va = *(const ulonglong2*)(vp);
            ulonglong2 vb = *(const ulonglong2*)(vp + 4);
            ulonglong2 vc = *(const ulonglong2*)(vp + 8);
            ulonglong2 vd = *(const ulonglong2*)(vp + 12);
            o2[0] = fma2(pp, va.x, o2[0]);
            o2[1] = fma2(pp, va.y, o2[1]);
            o2[2] = fma2(pp, vb.x, o2[2]);
            o2[3] = fma2(pp, vb.y, o2[3]);
            o2[4] = fma2(pp, vc.x, o2[4]);
            o2[5] = fma2(pp, vc.y, o2[5]);
            o2[6] = fma2(pp, vd.x, o2[6]);
            o2[7] = fma2(pp, vd.y, o2[7]);
        }
        __syncthreads();   // before next tile overwrites KVs
    }

    float inv_l = 1.0f / l_i;
    float oo[16];
    #pragma unroll
    for (int i = 0; i < 8; i++){
        float lo, hi; upk2(o2[i], lo, hi);
        oo[2*i]   = lo * inv_l;
        oo[2*i+1] = hi * inv_l;
    }
    size_t obase = base + (size_t)(qt*32 + row)*C_ + g*16;
    #pragma unroll
    for (int j = 0; j < 4; j++)
        *(float4*)(Og + obase + j*4) = make_float4(oo[4*j],oo[4*j+1],oo[4*j+2],oo[4*j+3]);
}

// ---------------------------------------------------------------- launch
extern "C" void kernel_launch(void* const* d_in, const int* in_sizes, int n_in,
                              void* d_out, int out_size)
{
    const float* x     = (const float*)d_in[0];
    const float* timep = (const float*)d_in[1];
    const float* label = (const float*)d_in[2];
    const float* xmask = (const float*)d_in[3];
    const float* Wl    = (const float*)d_in[4];
    const float* bl    = (const float*)d_in[5];
    const float* Wq    = (const float*)d_in[6];
    const float* Wk    = (const float*)d_in[7];
    const float* Wv    = (const float*)d_in[8];
    const float* W1    = (const float*)d_in[9];
    const float* b1    = (const float*)d_in[10];
    const float* W2    = (const float*)d_in[11];
    const float* b2    = (const float*)d_in[12];
    const float* Wm    = (const float*)d_in[13];
    const float* bm    = (const float*)d_in[14];
    const float* Wf    = (const float*)d_in[15];
    const float* bf    = (const float*)d_in[16];
    const float* Wmf   = (const float*)d_in[17];
    const float* bmf   = (const float*)d_in[18];

    float *xc,*h,*q,*k,*v,*att,*mid,*ffn,*cbuf,*cs,*modall,*modf;
    cudaGetSymbolAddress((void**)&xc,  g_xc);
    cudaGetSymbolAddress((void**)&h,   g_h);
    cudaGetSymbolAddress((void**)&q,   g_q);
    cudaGetSymbolAddress((void**)&k,   g_k);
    cudaGetSymbolAddress((void**)&v,   g_v);
    cudaGetSymbolAddress((void**)&att, g_att);
    cudaGetSymbolAddress((void**)&mid, g_mid);
    cudaGetSymbolAddress((void**)&ffn, g_ffn);
    cudaGetSymbolAddress((void**)&cbuf,g_c);
    cudaGetSymbolAddress((void**)&cs,  g_cs);
    cudaGetSymbolAddress((void**)&modall,g_modall);
    cudaGetSymbolAddress((void**)&modf,g_modf);

    cond_kernel<<<(B_*C_)/256, 256>>>(timep, label, Wl, bl, cbuf, cs);

    // ALL layers' mod vectors in one launch: rows = L*6C, Wm contiguous [L,6C,C]
    mod_gemm<<<MODR_/8, 256>>>(cs, Wm, bm, modall, MODR_);
    // final-projection mod (small; could fold in but layout differs)
    mod_gemm<<<(2*C_)/8, 256>>>(cs, Wmf, bmf, modf, 2*C_);

    dim3 gC(C_/128, BN_/128);       // (8,32)
    dim3 gQKV(C_/128, BN_/128, 3);  // (8,32,3)
    dim3 g4C(4*C_/128, BN_/128);    // (32,32)
    dim3 gAtt(N_/32, B_*H_);        // (16,128)

    for (int l = 0; l < L_; l++){
        int mb = l * 6*C_;              // this layer's base offset inside modall
        int pb = (l-1) * 6*C_;          // previous layer's base (l>=1 only)
        if (l == 0){
            // LN1: read input x directly (no residual, read-only), mask on h
            ln_mod<<<BN_, 256>>>(x, xc, h, modall, mb + 0, mb + C_, MODR_, xmask,
                                 nullptr, nullptr, 0, 0, nullptr);
        } else {
            // LN1 with deferred FFN residual from layer l-1: xc = (xc + gf_prev*ffn)*xm
            ln_mod<<<BN_, 256>>>(xc, xc, h, modall, mb + 0, mb + C_, MODR_, xmask,
                                 ffn, modall, pb + 5*C_, MODR_, xmask);
        }
        sgemm_qkv<<<gQKV, 256>>>(h, Wq + (size_t)l*C_*C_, Wk + (size_t)l*C_*C_, Wv + (size_t)l*C_*C_, q, k, v);
        attn_kernel<<<gAtt, 128>>>(q, k, v, xmask, att);
        // LN2 with fused attn gated residual: xc = resin + gm*att (persisted, no mask)
        ln_mod<<<BN_, 256>>>((l == 0) ? x : xc, xc, h, modall, mb + 3*C_, mb + 4*C_, MODR_, nullptr,
                             att, modall, mb + 2*C_, MODR_, nullptr);
        sgemm_nt<<<g4C, 256>>>(h, W1 + (size_t)l*4*C_*C_, b1 + (size_t)l*4*C_, nullptr, mid, BN_, 4*C_, C_, 1);
        sgemm_nt<<<gC, 256>>>(mid, W2 + (size_t)l*C_*4*C_, b2 + (size_t)l*C_, nullptr, ffn, BN_, C_, 4*C_, 0);
        // FFN gated residual deferred to next ln_mod (or the final one below)
    }

    // final LN with deferred layer-7 FFN residual: xc = (xc + gf*ffn)*xm, then h = mod(LN(xc))
    ln_mod<<<BN_, 256>>>(xc, xc, h, modf, 0, C_, 2*C_, nullptr,
                         ffn, modall, (L_-1)*6*C_ + 5*C_, MODR_, xmask);
    sgemm_nt<<<gC, 256>>>(h, Wf, bf, xmask, (float*)d_out, BN_, C_, C_, 0);
}

// round 10
// speedup vs baseline: 1.6444x; 1.6444x over previous
#include <cuda_runtime.h>
#include <math.h>

#define B_ 8
#define N_ 512
#define C_ 1024
#define H_ 16
#define D_ 64
#define L_ 8
#define BN_ (B_*N_)
#define BNC_ (B_*N_*C_)
#define MODR_ (L_*6*C_)      // total mod rows across all layers
#define PAD_ 136             // smem row pad: 136 mod 32 = 8 -> conflict-free fragment loads

// ---------------------------------------------------------------- f32x2 helpers (attention)
__device__ __forceinline__ unsigned long long pk2(float lo, float hi){
    unsigned long long r;
    asm("mov.b64 %0, {%1,%2};" : "=l"(r) : "f"(lo), "f"(hi));
    return r;
}
__device__ __forceinline__ void upk2(unsigned long long v, float& lo, float& hi){
    asm("mov.b64 {%0,%1}, %2;" : "=f"(lo), "=f"(hi) : "l"(v));
}
__device__ __forceinline__ unsigned long long fma2(unsigned long long a, unsigned long long b, unsigned long long c){
    unsigned long long d;
    asm("fma.rn.f32x2 %0, %1, %2, %3;" : "=l"(d) : "l"(a), "l"(b), "l"(c));
    return d;
}
__device__ __forceinline__ unsigned long long mul2(unsigned long long a, unsigned long long b){
    unsigned long long d;
    asm("mul.rn.f32x2 %0, %1, %2;" : "=l"(d) : "l"(a), "l"(b));
    return d;
}

// ---------------------------------------------------------------- tf32 helpers (GEMM)
__device__ __forceinline__ float tf32f(float x){
    unsigned r;
    asm("cvt.rna.tf32.f32 %0, %1;" : "=r"(r) : "f"(x));
    return __uint_as_float(r);
}
__device__ __forceinline__ void mma_tf32(float (&d)[4], const unsigned (&a)[4], const unsigned (&b)[2]){
    asm volatile(
        "mma.sync.aligned.m16n8k8.row.col.f32.tf32.tf32.f32 "
        "{%0,%1,%2,%3}, {%4,%5,%6,%7}, {%8,%9}, {%0,%1,%2,%3};"
        : "+f"(d[0]), "+f"(d[1]), "+f"(d[2]), "+f"(d[3])
        : "r"(a[0]), "r"(a[1]), "r"(a[2]), "r"(a[3]), "r"(b[0]), "r"(b[1]));
}

__device__ __forceinline__ float selu_f(float x){
    return 1.0507009873554805f * (x > 0.0f ? x : 1.6732632423543772f * expm1f(x));
}

// ---------------------------------------------------------------- scratch (no allocs allowed)
__device__ __align__(256) float g_xc [BNC_];
__device__ __align__(256) float g_h  [BNC_];
__device__ __align__(256) float g_q  [BNC_];
__device__ __align__(256) float g_k  [BNC_];
__device__ __align__(256) float g_v  [BNC_];
__device__ __align__(256) float g_att[BNC_];
__device__ __align__(256) float g_mid[B_*N_*4*C_];
__device__ __align__(256) float g_ffn[BNC_];
__device__ __align__(256) float g_c  [B_*C_];
__device__ __align__(256) float g_cs [B_*C_];
__device__ __align__(256) float g_modall[B_*MODR_];   // all layers' mod vectors [B][L*6C]
__device__ __align__(256) float g_modf[B_*2*C_];      // final-projection mod

// ---------------------------------------------------------------- conditioning
__global__ void cond_kernel(const float* __restrict__ timep, const float* __restrict__ label,
                            const float* __restrict__ Wl, const float* __restrict__ bl,
                            float* __restrict__ c_out, float* __restrict__ cs_out)
{
    int idx = blockIdx.x * 256 + threadIdx.x;
    if (idx >= B_*C_) return;
    int b = idx >> 10, j = idx & (C_-1);
    float lemb = label[b*2+0]*Wl[j*2+0] + label[b*2+1]*Wl[j*2+1] + bl[j];
    const float LOG1E4 = 9.210340371976184f;
    float base = expf((2.0f * (float)j / (float)C_) * LOG1E4);
    float te = timep[b] / base;
    te = ((j & 1) == 0) ? sinf(te) : cosf(te);
    float cv = lemb + te;
    c_out[idx]  = cv;
    cs_out[idx] = selu_f(cv);
}

// ---------------------------------------------------------------- mod = selu(c) @ W.T + b
__global__ void mod_gemm(const float* __restrict__ scv, const float* __restrict__ W,
                         const float* __restrict__ bias, float* __restrict__ out, int rows)
{
    __shared__ float s[B_*C_];
    int t = threadIdx.x;
    for (int i = t; i < B_*C_; i += 256) s[i] = scv[i];
    __syncthreads();
    int warp = t >> 5, lane = t & 31;
    int r = blockIdx.x * 8 + warp;
    if (r >= rows) return;
    float acc[B_] = {0,0,0,0,0,0,0,0};
    const float* wr = W + (size_t)r * C_;
    for (int k0 = lane*4; k0 < C_; k0 += 128){
        float4 w4 = *(const float4*)(wr + k0);
        #pragma unroll
        for (int b = 0; b < B_; b++){
            const float* sb = s + b*C_ + k0;
            acc[b] += w4.x*sb[0] + w4.y*sb[1] + w4.z*sb[2] + w4.w*sb[3];
        }
    }
    #pragma unroll
    for (int b = 0; b < B_; b++){
        #pragma unroll
        for (int off = 16; off > 0; off >>= 1)
            acc[b] += __shfl_down_sync(0xffffffffu, acc[b], off);
    }
    if (lane == 0){
        float bb = bias[r];
        #pragma unroll
        for (int b = 0; b < B_; b++) out[b*rows + r] = acc[b] + bb;
    }
}

// ---------------------------------------------------------------- fused [gated residual +] LN + modulate
__global__ void ln_mod(const float* __restrict__ resin, float* __restrict__ xcin,
                       float* __restrict__ out,
                       const float* __restrict__ mod, int shift_ofs, int scale_ofs, int modstride,
                       const float* __restrict__ xm_h,
                       const float* __restrict__ src,
                       const float* __restrict__ gmod, int gofs, int gstride,
                       const float* __restrict__ xm_res)
{
    __shared__ float rs[8], rq[8];
    int bn = blockIdx.x;
    int b  = bn >> 9;
    const float* rin = resin + ((size_t)bn << 10);
    float* row = xcin + ((size_t)bn << 10);
    int t = threadIdx.x;
    const float* gp = gmod ? (gmod + (size_t)b*gstride + gofs) : nullptr;
    float mres = xm_res ? xm_res[bn] : 1.0f;
    float v[4]; float s = 0.f, sq = 0.f;
    #pragma unroll
    for (int i = 0; i < 4; i++){
        int j = t + 256*i;
        float xv = rin[j];
        if (src){
            xv = (xv + gp[j] * src[((size_t)bn << 10) + j]) * mres;
            row[j] = xv;
        }
        v[i] = xv; s += xv; sq += xv*xv;
    }
    #pragma unroll
    for (int off = 16; off > 0; off >>= 1){
        s  += __shfl_down_sync(0xffffffffu, s,  off);
        sq += __shfl_down_sync(0xffffffffu, sq, off);
    }
    int warp = t >> 5, lane = t & 31;
    if (lane == 0){ rs[warp] = s; rq[warp] = sq; }
    __syncthreads();
    float S = 0.f, Q = 0.f;
    #pragma unroll
    for (int i = 0; i < 8; i++){ S += rs[i]; Q += rq[i]; }
    float mean = S * (1.0f/C_);
    float var  = Q * (1.0f/C_) - mean*mean;
    float rstd = rsqrtf(var + 1e-6f);
    float mk = xm_h ? xm_h[bn] : 1.0f;
    const float* shp = mod + (size_t)b*modstride + shift_ofs;
    const float* scp = mod + (size_t)b*modstride + scale_ofs;
    float* orow = out + ((size_t)bn << 10);
    #pragma unroll
    for (int i = 0; i < 4; i++){
        int j = t + 256*i;
        float val = (v[i] - mean) * rstd * (1.0f + scp[j]) + shp[j];
        orow[j] = val * mk;
    }
}

// ---------------------------------------------------------------- GEMM core: TF32 tensor-core mma, double-buffered smem
// C[128,128] tile of A[M,K] @ W[Nc,K]^T.  8 warps, each 64x32 (4x4 m16n8k8 tiles).
// smem layout: As[k][row] (k-major), values pre-converted to tf32.
__device__ __forceinline__ void gemm_tile(const float* __restrict__ A, const float* __restrict__ W,
                                          int K, int bx, int by,
                                          float (*As)[PAD_], float (*Bs)[PAD_],   // [2*16][PAD_]
                                          float (&acc)[4][4][4])
{
    int t  = threadIdx.x;
    int lr = t >> 1;                 // 0..127 staging row
    int lc = (t & 1) << 2;           // 0 or 4
    int lane = t & 31, w = t >> 5;
    int wm = w & 1, wn = w >> 1;     // warp tile: rows [wm*64,+64), cols [wn*32,+32)
    int q = lane >> 2, c = lane & 3; // quad row / quad lane
    const float* Ag = A + ((size_t)by*128 + lr) * K + lc;
    const float* Wg = W + ((size_t)bx*128 + lr) * K + lc;
    #pragma unroll
    for (int mt = 0; mt < 4; mt++)
        #pragma unroll
        for (int nt = 0; nt < 4; nt++)
            #pragma unroll
            for (int i = 0; i < 4; i++) acc[mt][nt][i] = 0.0f;

    // prologue: fetch slice 0 (16 wide = 2 float4 per matrix per thread)
    float4 a4  = *(const float4*)(Ag);
    float4 a4h = *(const float4*)(Ag + 8);
    float4 b4  = *(const float4*)(Wg);
    float4 b4h = *(const float4*)(Wg + 8);

    int buf = 0;
    for (int k0 = 0; k0 < K; k0 += 16){
        float (*Asb)[PAD_] = As + buf*16;
        float (*Bsb)[PAD_] = Bs + buf*16;
        // stage with tf32 rounding baked in
        Asb[lc+0][lr]=tf32f(a4.x);  Asb[lc+1][lr]=tf32f(a4.y);  Asb[lc+2][lr]=tf32f(a4.z);  Asb[lc+3][lr]=tf32f(a4.w);
        Asb[lc+8][lr]=tf32f(a4h.x); Asb[lc+9][lr]=tf32f(a4h.y); Asb[lc+10][lr]=tf32f(a4h.z); Asb[lc+11][lr]=tf32f(a4h.w);
        Bsb[lc+0][lr]=tf32f(b4.x);  Bsb[lc+1][lr]=tf32f(b4.y);  Bsb[lc+2][lr]=tf32f(b4.z);  Bsb[lc+3][lr]=tf32f(b4.w);
        Bsb[lc+8][lr]=tf32f(b4h.x); Bsb[lc+9][lr]=tf32f(b4h.y); Bsb[lc+10][lr]=tf32f(b4h.z); Bsb[lc+11][lr]=tf32f(b4h.w);
        __syncthreads();

        if (k0 + 16 < K){
            a4  = *(const float4*)(Ag + k0 + 16);
            a4h = *(const float4*)(Ag + k0 + 24);
            b4  = *(const float4*)(Wg + k0 + 16);
            b4h = *(const float4*)(Wg + k0 + 24);
        }

        #pragma unroll
        for (int ks = 0; ks < 2; ks++){
            int kb = ks * 8;
            unsigned af[4][4], bf[4][2];
            #pragma unroll
            for (int mt = 0; mt < 4; mt++){
                int ar = wm*64 + mt*16 + q;
                af[mt][0] = __float_as_uint(Asb[kb + c    ][ar    ]);
                af[mt][1] = __float_as_uint(Asb[kb + c    ][ar + 8]);
                af[mt][2] = __float_as_uint(Asb[kb + c + 4][ar    ]);
                af[mt][3] = __float_as_uint(Asb[kb + c + 4][ar + 8]);
            }
            #pragma unroll
            for (int nt = 0; nt < 4; nt++){
                int bc = wn*32 + nt*8 + q;
                bf[nt][0] = __float_as_uint(Bsb[kb + c    ][bc]);
                bf[nt][1] = __float_as_uint(Bsb[kb + c + 4][bc]);
            }
            #pragma unroll
            for (int mt = 0; mt < 4; mt++)
                #pragma unroll
                for (int nt = 0; nt < 4; nt++)
                    mma_tf32(acc[mt][nt], af[mt], bf[nt]);
        }
        buf ^= 1;   // WAR-safe: barrier-i guarantees compute i-1 done
    }
}

// general single-output GEMM with fused epilogue
__global__ void __launch_bounds__(256, 2)
sgemm_nt(const float* __restrict__ A, const float* __restrict__ W,
         const float* __restrict__ bias, const float* __restrict__ rowmask,
         float* __restrict__ Cmat, int M, int Ncols, int K, int act)
{
    __shared__ __align__(16) float As[32][PAD_];
    __shared__ __align__(16) float Bs[32][PAD_];
    float acc[4][4][4];
    gemm_tile(A, W, K, blockIdx.x, blockIdx.y, As, Bs, acc);

    int t = threadIdx.x, lane = t & 31, w = t >> 5;
    int wm = w & 1, wn = w >> 1;
    int q = lane >> 2, c = lane & 3;
    #pragma unroll
    for (int mt = 0; mt < 4; mt++){
        int row0 = blockIdx.y*128 + wm*64 + mt*16 + q;
        #pragma unroll
        for (int rr = 0; rr < 2; rr++){
            int row = row0 + rr*8;
            float mk = rowmask ? rowmask[row] : 1.0f;
            #pragma unroll
            for (int nt = 0; nt < 4; nt++){
                int col = blockIdx.x*128 + wn*32 + nt*8 + 2*c;
                float v0 = acc[mt][nt][2*rr + 0];
                float v1 = acc[mt][nt][2*rr + 1];
                if (bias){ v0 += bias[col]; v1 += bias[col+1]; }
                if (act){ v0 = selu_f(v0); v1 = selu_f(v1); }
                *(float2*)(Cmat + (size_t)row*Ncols + col) = make_float2(v0*mk, v1*mk);
            }
        }
    }
}

// fused Q/K/V projection: blockIdx.z selects weight + destination
__global__ void __launch_bounds__(256, 2)
sgemm_qkv(const float* __restrict__ A,
          const float* __restrict__ Wq, const float* __restrict__ Wk, const float* __restrict__ Wv,
          float* __restrict__ Qo, float* __restrict__ Ko, float* __restrict__ Vo)
{
    __shared__ __align__(16) float As[32][PAD_];
    __shared__ __align__(16) float Bs[32][PAD_];
    const float* W = (blockIdx.z == 0) ? Wq : (blockIdx.z == 1) ? Wk : Wv;
    float* Cmat    = (blockIdx.z == 0) ? Qo : (blockIdx.z == 1) ? Ko : Vo;
    float acc[4][4][4];
    gemm_tile(A, W, C_, blockIdx.x, blockIdx.y, As, Bs, acc);

    int t = threadIdx.x, lane = t & 31, w = t >> 5;
    int wm = w & 1, wn = w >> 1;
    int q = lane >> 2, c = lane & 3;
    #pragma unroll
    for (int mt = 0; mt < 4; mt++){
        int row0 = blockIdx.y*128 + wm*64 + mt*16 + q;
        #pragma unroll
        for (int rr = 0; rr < 2; rr++){
            int row = row0 + rr*8;
            #pragma unroll
            for (int nt = 0; nt < 4; nt++){
                int col = blockIdx.x*128 + wn*32 + nt*8 + 2*c;
                *(float2*)(Cmat + (size_t)row*C_ + col) =
                    make_float2(acc[mt][nt][2*rr + 0], acc[mt][nt][2*rr + 1]);
            }
        }
    }
}

// ---------------------------------------------------------------- flash attention (unchanged, f32x2)
#define AP 68
__global__ void __launch_bounds__(128, 4)
attn_kernel(const float* __restrict__ Qg, const float* __restrict__ Kg,
            const float* __restrict__ Vg, const float* __restrict__ xm,
            float* __restrict__ Og)
{
    __shared__ __align__(16) float Qs [32*AP];
    __shared__ __align__(16) float KVs[64*AP];
    __shared__ __align__(16) float Ps [32*AP];
    __shared__ float xmk[64];

    int qt = blockIdx.x;
    int bh = blockIdx.y;
    int b = bh >> 4, h = bh & 15;
    int t = threadIdx.x;
    const float inv_tp = rsqrtf(2.0f * (float)D_);

    size_t base = ((size_t)b * N_) * C_ + (size_t)h * D_;

    for (int i = t; i < 32*16; i += 128){
        int r = i >> 4, d4 = i & 15;
        float4 qv = *(const float4*)(Qg + base + (size_t)(qt*32 + r)*C_ + d4*4);
        qv.x *= inv_tp; qv.y *= inv_tp; qv.z *= inv_tp; qv.w *= inv_tp;
        *(float4*)(Qs + r*AP + d4*4) = qv;
    }
    int row = t >> 2, g = t & 3;
    float xq = xm[b*N_ + qt*32 + row];
    float m_i = -INFINITY, l_i = 0.0f;
    unsigned long long o2[8];
    #pragma unroll
    for (int i = 0; i < 8; i++) o2[i] = 0ULL;
    __syncthreads();

    for (int kt = 0; kt < 8; kt++){
        for (int i = t; i < 64*16; i += 128){
            int r = i >> 4, d4 = i & 15;
            *(float4*)(KVs + r*AP + d4*4) =
                *(const float4*)(Kg + base + (size_t)(kt*64 + r)*C_ + d4*4);
        }
        if (t < 64) xmk[t] = xm[b*N_ + kt*64 + t];
        __syncthreads();

        unsigned long long s2[16];
        #pragma unroll
        for (int jj = 0; jj < 16; jj++) s2[jj] = 0ULL;
        #pragma unroll
        for (int d4 = 0; d4 < 16; d4++){
            ulonglong2 q2 = *(const ulonglong2*)(Qs + row*AP + d4*4);
            #pragma unroll
            for (int jj = 0; jj < 16; jj++){
                ulonglong2 k2 = *(const ulonglong2*)(KVs + (g + 4*jj)*AP + d4*4);
                s2[jj] = fma2(q2.x, k2.x, s2[jj]);
                s2[jj] = fma2(q2.y, k2.y, s2[jj]);
            }
        }
        float sv[16]; float tmax = -INFINITY;
        #pragma unroll
        for (int jj = 0; jj < 16; jj++){
            float lo, hi; upk2(s2[jj], lo, hi);
            float val = lo + hi;
            if (xq + xmk[g + 4*jj] == 1.0f) val = -INFINITY;
            sv[jj] = val;
            tmax = fmaxf(tmax, val);
        }
        tmax = fmaxf(tmax, __shfl_xor_sync(0xffffffffu, tmax, 1));
        tmax = fmaxf(tmax, __shfl_xor_sync(0xffffffffu, tmax, 2));
        float m_new = fmaxf(m_i, tmax);
        float f, tsum = 0.0f;
        if (m_new == -INFINITY){
            f = 1.0f;
            #pragma unroll
            for (int jj = 0; jj < 16; jj++) Ps[row*AP + g + 4*jj] = 0.0f;
        } else {
            f = __expf(m_i - m_new);
            #pragma unroll
            for (int jj = 0; jj < 16; jj++){
                float p = __expf(sv[jj] - m_new);
                tsum += p;
                Ps[row*AP + g + 4*jj] = p;
            }
        }
        tsum += __shfl_xor_sync(0xffffffffu, tsum, 1);
        tsum += __shfl_xor_sync(0xffffffffu, tsum, 2);
        m_i = m_new;
        l_i = l_i * f + tsum;
        {
            unsigned long long ff = pk2(f, f);
            #pragma unroll
            for (int i = 0; i < 8; i++) o2[i] = mul2(o2[i], ff);
        }
        __syncthreads();

        for (int i = t; i < 64*16; i += 128){
            int r = i >> 4, d4 = i & 15;
            *(float4*)(KVs + r*AP + d4*4) =
                *(const float4*)(Vg + base + (size_t)(kt*64 + r)*C_ + d4*4);
        }
        __syncthreads();

        for (int kk = 0; kk < 64; kk++){
            float p = Ps[row*AP + kk];
            unsigned long long pp = pk2(p, p);
            const float* vp = KVs + kk*AP + g*16;
            ulonglong2 va = *(const ulonglong2*)(vp);
            ulonglong2 vb = *(const ulonglong2*)(vp + 4);
            ulonglong2 vc = *(const ulonglong2*)(vp + 8);
            ulonglong2 vd = *(const ulonglong2*)(vp + 12);
            o2[0] = fma2(pp, va.x, o2[0]);
            o2[1] = fma2(pp, va.y, o2[1]);
            o2[2] = fma2(pp, vb.x, o2[2]);
            o2[3] = fma2(pp, vb.y, o2[3]);
            o2[4] = fma2(pp, vc.x, o2[4]);
            o2[5] = fma2(pp, vc.y, o2[5]);
            o2[6] = fma2(pp, vd.x, o2[6]);
            o2[7] = fma2(pp, vd.y, o2[7]);
        }
        __syncthreads();
    }

    float inv_l = 1.0f / l_i;
    float oo[16];
    #pragma unroll
    for (int i = 0; i < 8; i++){
        float lo, hi; upk2(o2[i], lo, hi);
        oo[2*i]   = lo * inv_l;
        oo[2*i+1] = hi * inv_l;
    }
    size_t obase = base + (size_t)(qt*32 + row)*C_ + g*16;
    #pragma unroll
    for (int j = 0; j < 4; j++)
        *(float4*)(Og + obase + j*4) = make_float4(oo[4*j],oo[4*j+1],oo[4*j+2],oo[4*j+3]);
}

// ---------------------------------------------------------------- launch
extern "C" void kernel_launch(void* const* d_in, const int* in_sizes, int n_in,
                              void* d_out, int out_size)
{
    const float* x     = (const float*)d_in[0];
    const float* timep = (const float*)d_in[1];
    const float* label = (const float*)d_in[2];
    const float* xmask = (const float*)d_in[3];
    const float* Wl    = (const float*)d_in[4];
    const float* bl    = (const float*)d_in[5];
    const float* Wq    = (const float*)d_in[6];
    const float* Wk    = (const float*)d_in[7];
    const float* Wv    = (const float*)d_in[8];
    const float* W1    = (const float*)d_in[9];
    const float* b1    = (const float*)d_in[10];
    const float* W2    = (const float*)d_in[11];
    const float* b2    = (const float*)d_in[12];
    const float* Wm    = (const float*)d_in[13];
    const float* bm    = (const float*)d_in[14];
    const float* Wf    = (const float*)d_in[15];
    const float* bf    = (const float*)d_in[16];
    const float* Wmf   = (const float*)d_in[17];
    const float* bmf   = (const float*)d_in[18];

    float *xc,*h,*q,*k,*v,*att,*mid,*ffn,*cbuf,*cs,*modall,*modf;
    cudaGetSymbolAddress((void**)&xc,  g_xc);
    cudaGetSymbolAddress((void**)&h,   g_h);
    cudaGetSymbolAddress((void**)&q,   g_q);
    cudaGetSymbolAddress((void**)&k,   g_k);
    cudaGetSymbolAddress((void**)&v,   g_v);
    cudaGetSymbolAddress((void**)&att, g_att);
    cudaGetSymbolAddress((void**)&mid, g_mid);
    cudaGetSymbolAddress((void**)&ffn, g_ffn);
    cudaGetSymbolAddress((void**)&cbuf,g_c);
    cudaGetSymbolAddress((void**)&cs,  g_cs);
    cudaGetSymbolAddress((void**)&modall,g_modall);
    cudaGetSymbolAddress((void**)&modf,g_modf);

    cond_kernel<<<(B_*C_)/256, 256>>>(timep, label, Wl, bl, cbuf, cs);

    mod_gemm<<<MODR_/8, 256>>>(cs, Wm, bm, modall, MODR_);
    mod_gemm<<<(2*C_)/8, 256>>>(cs, Wmf, bmf, modf, 2*C_);

    dim3 gC(C_/128, BN_/128);       // (8,32)
    dim3 gQKV(C_/128, BN_/128, 3);  // (8,32,3)
    dim3 g4C(4*C_/128, BN_/128);    // (32,32)
    dim3 gAtt(N_/32, B_*H_);        // (16,128)

    for (int l = 0; l < L_; l++){
        int mb = l * 6*C_;
        int pb = (l-1) * 6*C_;
        if (l == 0){
            ln_mod<<<BN_, 256>>>(x, xc, h, modall, mb + 0, mb + C_, MODR_, xmask,
                                 nullptr, nullptr, 0, 0, nullptr);
        } else {
            ln_mod<<<BN_, 256>>>(xc, xc, h, modall, mb + 0, mb + C_, MODR_, xmask,
                                 ffn, modall, pb + 5*C_, MODR_, xmask);
        }
        sgemm_qkv<<<gQKV, 256>>>(h, Wq + (size_t)l*C_*C_, Wk + (size_t)l*C_*C_, Wv + (size_t)l*C_*C_, q, k, v);
        attn_kernel<<<gAtt, 128>>>(q, k, v, xmask, att);
        ln_mod<<<BN_, 256>>>((l == 0) ? x : xc, xc, h, modall, mb + 3*C_, mb + 4*C_, MODR_, nullptr,
                             att, modall, mb + 2*C_, MODR_, nullptr);
        sgemm_nt<<<g4C, 256>>>(h, W1 + (size_t)l*4*C_*C_, b1 + (size_t)l*4*C_, nullptr, mid, BN_, 4*C_, C_, 1);
        sgemm_nt<<<gC, 256>>>(mid, W2 + (size_t)l*C_*4*C_, b2 + (size_t)l*C_, nullptr, ffn, BN_, C_, 4*C_, 0);
    }

    ln_mod<<<BN_, 256>>>(xc, xc, h, modf, 0, C_, 2*C_, nullptr,
                         ffn, modall, (L_-1)*6*C_ + 5*C_, MODR_, xmask);
    sgemm_nt<<<gC, 256>>>(h, Wf, bf, xmask, (float*)d_out, BN_, C_, C_, 0);
}